// round 8
// baseline (speedup 1.0000x reference)
#include <cuda_runtime.h>
#include <math.h>

// Problem constants: B=4, N=8192, D=64, K=16
#define BB 4
#define NN 8192
#define KK 16
#define KP 8          // K/2 float2 pairs
#define MC 2048       // m-tile width (columns of W per block)
#define MH (MC / 2)   // half tile (even/odd split)
#define TPB 512       // threads per block (16 warps)
#define RPW 4         // rows per warp
#define RPB 64        // rows per block (16 warps * 4)
#define NIT (MC / 64) // inner iterations (64 m per iter per warp)

typedef unsigned long long u64;

// Global accumulators + scratch (device globals: no allocation allowed)
__device__ double g_TR;              // sum_b trace(cut_b)
__device__ double g_CS;              // sum of all W
__device__ float  g_StS[BB * KK * KK];
__device__ float  g_Sscratch[BB * NN * KK];  // fallback if d_out lacks room for S

__device__ __forceinline__ u64 ffma2(u64 a, u64 b, u64 c) {
    u64 d;
    asm("fma.rn.f32x2 %0, %1, %2, %3;" : "=l"(d) : "l"(a), "l"(b), "l"(c));
    return d;
}
__device__ __forceinline__ u64 addf2(u64 a, u64 b) {
    u64 d;
    asm("add.rn.f32x2 %0, %1, %2;" : "=l"(d) : "l"(a), "l"(b));
    return d;
}
__device__ __forceinline__ u64 pack2(float x) {
    u64 d;
    asm("mov.b64 %0, {%1, %1};" : "=l"(d) : "f"(x));
    return d;
}
__device__ __forceinline__ float2 unpack2(u64 v) {
    float2 r;
    asm("mov.b64 {%0, %1}, %2;" : "=f"(r.x), "=f"(r.y) : "l"(v));
    return r;
}
// Streaming (evict-first) 64-bit global load: W has zero reuse, keep it out
// of L2's working set so the S tile stays resident.
__device__ __forceinline__ float2 ldcs2(const float2* p) {
    float2 v;
    asm("ld.global.cs.v2.f32 {%0, %1}, [%2];"
        : "=f"(v.x), "=f"(v.y) : "l"(p));
    return v;
}

// ---------------------------------------------------------------------------
// Kernel 0: zero accumulators (graph-replay safe re-init)
// ---------------------------------------------------------------------------
__global__ void zero_kernel() {
    int t = threadIdx.x;
    if (t == 0) { g_TR = 0.0; g_CS = 0.0; }
    if (t < BB * KK * KK) g_StS[t] = 0.0f;
}

// ---------------------------------------------------------------------------
// Kernel 1: softmax over K=16 (writes S) fused with StS partials.
// grid: (B, N/256), block: 256 threads, one row per thread.
// ---------------------------------------------------------------------------
__global__ void softmax_sts_kernel(const float* __restrict__ logits,
                                   float* __restrict__ S) {
    __shared__ float sh[256 * 17];  // padded stride to dodge bank conflicts
    int b = blockIdx.x;
    int n = blockIdx.y * 256 + threadIdx.x;
    const float* lrow = logits + ((size_t)b * NN + n) * KK;
    float v[KK];
    float4 l0 = *reinterpret_cast<const float4*>(lrow + 0);
    float4 l1 = *reinterpret_cast<const float4*>(lrow + 4);
    float4 l2 = *reinterpret_cast<const float4*>(lrow + 8);
    float4 l3 = *reinterpret_cast<const float4*>(lrow + 12);
    v[0]=l0.x; v[1]=l0.y; v[2]=l0.z; v[3]=l0.w;
    v[4]=l1.x; v[5]=l1.y; v[6]=l1.z; v[7]=l1.w;
    v[8]=l2.x; v[9]=l2.y; v[10]=l2.z; v[11]=l2.w;
    v[12]=l3.x; v[13]=l3.y; v[14]=l3.z; v[15]=l3.w;
    float mx = v[0];
    #pragma unroll
    for (int i = 1; i < KK; ++i) mx = fmaxf(mx, v[i]);
    float sum = 0.0f;
    #pragma unroll
    for (int i = 0; i < KK; ++i) { v[i] = __expf(v[i] - mx); sum += v[i]; }
    float inv = 1.0f / sum;
    #pragma unroll
    for (int i = 0; i < KK; ++i) v[i] *= inv;

    float* srow = S + ((size_t)b * NN + n) * KK;
    *reinterpret_cast<float4*>(srow + 0)  = make_float4(v[0], v[1], v[2], v[3]);
    *reinterpret_cast<float4*>(srow + 4)  = make_float4(v[4], v[5], v[6], v[7]);
    *reinterpret_cast<float4*>(srow + 8)  = make_float4(v[8], v[9], v[10], v[11]);
    *reinterpret_cast<float4*>(srow + 12) = make_float4(v[12], v[13], v[14], v[15]);

    // stage rows, then each thread owns one (k,j) entry of StS partial
    #pragma unroll
    for (int i = 0; i < KK; ++i) sh[threadIdx.x * 17 + i] = v[i];
    __syncthreads();
    int k = threadIdx.x >> 4;
    int j = threadIdx.x & 15;
    float acc = 0.0f;
    #pragma unroll 8
    for (int r = 0; r < 256; ++r)
        acc += sh[r * 17 + k] * sh[r * 17 + j];
    atomicAdd(&g_StS[(b * KK + k) * KK + j], acc);
}

// ---------------------------------------------------------------------------
// Kernel 2: streaming pass over W. Computes
//   g_TR += sum_{n,m} W[b,n,m] * dot(S[b,n,:], S[b,m,:])
//   g_CS += sum W
// grid: (N/MC, N/RPB, B), block: 512 threads, 128 KB dynamic smem (S tile).
// Each warp owns 4 rows; lanes partition m as float2 pairs (coalesced LDG.64).
// S tile layout S2[kp][parity][m/2] (even/odd split): lane stride 8 B on
// LDS.64 -> each 16-lane phase hits all 32 banks exactly once, conflict-free.
// W prefetched distance-2 via rolling double buffer to cover DRAM latency;
// all W loads use the .cs (evict-first) policy.
// ---------------------------------------------------------------------------
__global__ void __launch_bounds__(TPB, 1)
wtrace_kernel(const float* __restrict__ W, const float* __restrict__ S) {
    extern __shared__ u64 S2[];  // [KP][2][MH]
    int b = blockIdx.z;
    int m0 = blockIdx.x * MC;
    const float* Sb = S + (size_t)b * NN * KK;

    // Fill S tile: S2[kp*MC + (m&1)*MH + (m>>1)] = S[m0+m, 2kp:2kp+2]
    for (int idx = threadIdx.x; idx < KP * MC; idx += TPB) {
        int kp = idx >> 11;          // idx / MC
        int m  = idx & (MC - 1);     // idx % MC
        float2 sv = __ldg(reinterpret_cast<const float2*>(
            Sb + (size_t)(m0 + m) * KK + 2 * kp));
        S2[kp * MC + (m & 1) * MH + (m >> 1)] = *reinterpret_cast<const u64*>(&sv);
    }
    __syncthreads();

    int warp = threadIdx.x >> 5;
    int lane = threadIdx.x & 31;
    int row0 = blockIdx.y * RPB + warp * RPW;

    // Single advancing W pointer; rows at compile-time immediate offsets.
    const float2* wb = reinterpret_cast<const float2*>(
        W + (size_t)b * NN * NN + (size_t)row0 * NN + m0) + lane;

    u64 acc[RPW][KP];
    #pragma unroll
    for (int r = 0; r < RPW; ++r)
        #pragma unroll
        for (int kp = 0; kp < KP; ++kp) acc[r][kp] = 0ULL;
    u64 wsum2 = 0ULL;

    // Distance-2 rolling prefetch buffers (evict-first loads)
    float2 bufA[RPW], bufB[RPW];
    #pragma unroll
    for (int r = 0; r < RPW; ++r) bufA[r] = ldcs2(wb + r * (NN / 2));
    #pragma unroll
    for (int r = 0; r < RPW; ++r) bufB[r] = ldcs2(wb + r * (NN / 2) + 32);

    const u64* sp = S2 + lane;

    #pragma unroll 2
    for (int i = 0; i < NIT; ++i) {
        u64 s[KP];
        // even-m sub-array (lane stride 8 B, conflict-free)
        #pragma unroll
        for (int kp = 0; kp < KP; ++kp) s[kp] = sp[kp * MC];
        #pragma unroll
        for (int r = 0; r < RPW; ++r) {
            float2 w = (i & 1) ? bufB[r] : bufA[r];
            u64 ww = pack2(w.x);
            #pragma unroll
            for (int kp = 0; kp < KP; ++kp)
                acc[r][kp] = ffma2(ww, s[kp], acc[r][kp]);
        }
        // odd-m sub-array
        #pragma unroll
        for (int kp = 0; kp < KP; ++kp) s[kp] = sp[kp * MC + MH];
        #pragma unroll
        for (int r = 0; r < RPW; ++r) {
            float2 w = (i & 1) ? bufB[r] : bufA[r];
            u64 ww = pack2(w.y);
            #pragma unroll
            for (int kp = 0; kp < KP; ++kp)
                acc[r][kp] = ffma2(ww, s[kp], acc[r][kp]);
            wsum2 = addf2(wsum2, *reinterpret_cast<const u64*>(&w));
        }
        // prefetch i+2 into the buffer just consumed
        if (i + 2 < NIT) {
            #pragma unroll
            for (int r = 0; r < RPW; ++r) {
                float2 nv = ldcs2(wb + r * (NN / 2) + 64);
                if (i & 1) bufB[r] = nv; else bufA[r] = nv;
            }
        }
        wb += 32;
        sp += 32;
    }

    // finalize: tr = sum_r dot(acc[r], S[row_r,:])
    float tr = 0.0f;
    #pragma unroll
    for (int r = 0; r < RPW; ++r) {
        const u64* srow = reinterpret_cast<const u64*>(
            Sb + (size_t)(row0 + r) * KK);
        #pragma unroll
        for (int kp = 0; kp < KP; ++kp) {
            u64 spacked = __ldg(srow + kp);
            float2 a = unpack2(acc[r][kp]);
            float2 sv = unpack2(spacked);
            tr += a.x * sv.x + a.y * sv.y;
        }
    }
    float2 wsp = unpack2(wsum2);
    float wsum = wsp.x + wsp.y;

    // warp reduce
    #pragma unroll
    for (int off = 16; off > 0; off >>= 1) {
        tr   += __shfl_down_sync(0xFFFFFFFFu, tr, off);
        wsum += __shfl_down_sync(0xFFFFFFFFu, wsum, off);
    }
    __shared__ float redT[TPB / 32];
    __shared__ float redW[TPB / 32];
    if (lane == 0) { redT[warp] = tr; redW[warp] = wsum; }
    __syncthreads();
    if (threadIdx.x == 0) {
        float a = 0.0f, c = 0.0f;
        #pragma unroll
        for (int w = 0; w < TPB / 32; ++w) { a += redT[w]; c += redW[w]; }
        atomicAdd(&g_TR, (double)a);
        atomicAdd(&g_CS, (double)c);
    }
}

// ---------------------------------------------------------------------------
// Kernel 3: combine: loss = -TR/CS + ||StS - I||_F / B
// ---------------------------------------------------------------------------
__global__ void final_kernel(float* __restrict__ out_loss) {
    __shared__ float red[8];
    int t = threadIdx.x;  // 256 threads, one (k,j) per thread across batches
    int k = t >> 4, j = t & 15;
    float v = 0.0f;
    #pragma unroll
    for (int b = 0; b < BB; ++b) {
        float x = g_StS[b * 256 + t] - (k == j ? 1.0f : 0.0f);
        v += x * x;
    }
    #pragma unroll
    for (int off = 16; off > 0; off >>= 1)
        v += __shfl_down_sync(0xFFFFFFFFu, v, off);
    if ((t & 31) == 0) red[t >> 5] = v;
    __syncthreads();
    if (t == 0) {
        float total = 0.0f;
        #pragma unroll
        for (int w = 0; w < 8; ++w) total += red[w];
        float ortho = sqrtf(total) / (float)BB;
        float cut_loss = (float)(g_TR / g_CS);
        *out_loss = -cut_loss + ortho;
    }
}

// ---------------------------------------------------------------------------
extern "C" void kernel_launch(void* const* d_in, const int* in_sizes, int n_in,
                              void* d_out, int out_size) {
    // Identify inputs by element count (robust to ordering):
    // features: B*N*D = 2097152, W: B*N*N = 268435456, logits: B*N*K = 524288
    const float* W = nullptr;
    const float* logits = nullptr;
    for (int i = 0; i < n_in; ++i) {
        if (in_sizes[i] == BB * NN * NN)      W = (const float*)d_in[i];
        else if (in_sizes[i] == BB * NN * KK) logits = (const float*)d_in[i];
    }
    float* out = (float*)d_out;

    // Output layout dispatch:
    //   out_size >= B*N*K+1 : [S, ..., loss at out_size-1]   (expected)
    //   out_size == B*N*K   : S only — do NOT clobber S with the loss
    //   smaller             : loss-only; S lives in device scratch
    float* S;
    bool write_loss = true;
    if (out_size >= BB * NN * KK + 1) {
        S = out;
    } else if (out_size == BB * NN * KK) {
        S = out;
        write_loss = false;
    } else {
        cudaGetSymbolAddress((void**)&S, g_Sscratch);  // host-side query, capture-safe
    }
    float* loss_ptr = out + (out_size - 1);

    cudaFuncSetAttribute(wtrace_kernel,
                         cudaFuncAttributeMaxDynamicSharedMemorySize,
                         KP * MC * (int)sizeof(u64));

    zero_kernel<<<1, 1024>>>();
    softmax_sts_kernel<<<dim3(BB, NN / 256), 256>>>(logits, S);
    if (write_loss) {
        wtrace_kernel<<<dim3(NN / MC, NN / RPB, BB), TPB,
                        KP * MC * sizeof(u64)>>>(W, S);
        final_kernel<<<1, 256>>>(loss_ptr);
    }
}